// round 14
// baseline (speedup 1.0000x reference)
#include <cuda_runtime.h>
#include <cuda_fp16.h>
#include <cstdint>

// ---------------- problem constants ----------------
#define BATCH   256
#define CIN     64
#define COUT    128
#define HX      1039
#define KNB     6
#define NSLOT   7
#define KD      448          // k extent (7 slots * 64)
#define BH      (BATCH * HX)
#define NTILE   64           // h per CTA tile
#define TPB     17           // tiles per batch: ceil(1039/64)
#define TOT_TILES (BATCH * TPB)   // 4352

// slot = [A-slice image 16KB][B rows 64 x 144B]
#define A_CHUNK   16384
#define B_ROWP    144                      // padded B row stride (16n bank shift)
#define B_CHUNK   (64 * B_ROWP)            // 9216
#define SLOT_B    (A_CHUNK + B_CHUNK)      // 25600 (25 * 1024)
#define NSTAGE    4
#define LOOKAHEAD 3
#define TXBYTES   (A_CHUNK + 64 * 128)     // 24576 per chunk
#define SMEM_TOTAL (1024 + NSTAGE * SLOT_B)   // 103424 -> 2 CTAs/SM

// ---------------- scratch ----------------
__device__ __align__(16)  __half g_xTh[(size_t)BATCH * HX * CIN];  // [b][h][c], 128B rows
__device__ __align__(128) char   g_Wslot[NSLOT * A_CHUNK];         // pre-swizzled A images
__device__ __align__(128) char   g_zero[128];                      // zero row (static init)
__device__ float  g_invd[HX];

// ---------------- helpers ----------------
static __device__ __forceinline__ uint32_t s2u(const void* p) {
    uint32_t a;
    asm("{ .reg .u64 t; cvta.to.shared.u64 t, %1; cvt.u32.u64 %0, t; }" : "=r"(a) : "l"(p));
    return a;
}
static __device__ __forceinline__ void bulk_g2s(uint32_t dst, const void* src,
                                                uint32_t size, uint32_t mbar) {
    asm volatile("cp.async.bulk.shared::cluster.global.mbarrier::complete_tx::bytes "
                 "[%0], [%1], %2, [%3];"
                 :: "r"(dst), "l"(src), "r"(size), "r"(mbar) : "memory");
}
#define MBARRIER_INIT(mb, c) \
    asm volatile("mbarrier.init.shared.b64 [%0], %1;" :: "r"((uint32_t)(mb)), "r"((uint32_t)(c)) : "memory")
#define MBARRIER_EXPECT_TX(mb, tx) \
    asm volatile("mbarrier.arrive.expect_tx.shared.b64 _, [%0], %1;" \
                 :: "r"((uint32_t)(mb)), "r"((uint32_t)(tx)) : "memory")
#define FENCE_PROXY_ASYNC() asm volatile("fence.proxy.async.shared::cta;" ::: "memory")
#define MBARRIER_WAIT_PARITY(mb, ph) do { \
    uint32_t _mb = (uint32_t)(mb), _ph = (uint32_t)(ph), _done; \
    asm volatile("{\n\t.reg .pred p;\n\tmbarrier.try_wait.parity.acquire.cta.shared::cta.b64 p, [%1], %2;\n\t" \
                 "selp.b32 %0, 1, 0, p;\n\t}" : "=r"(_done) : "r"(_mb), "r"(_ph) : "memory"); \
    if (!_done) { \
        asm volatile("{\n\t.reg .pred P1;\n\tWL_%=:\n\t" \
                     "mbarrier.try_wait.parity.acquire.cta.shared::cta.b64 P1, [%0], %1, 0x989680;\n\t" \
                     "@P1 bra.uni WD_%=;\n\tbra.uni WL_%=;\n\tWD_%=:\n\t}" \
                     :: "r"(_mb), "r"(_ph) : "memory"); \
    } \
} while (0)
static __device__ __forceinline__ void ldsm4(uint32_t* d, uint32_t addr) {
    asm volatile("ldmatrix.sync.aligned.m8n8.x4.shared.b16 {%0,%1,%2,%3}, [%4];"
                 : "=r"(d[0]), "=r"(d[1]), "=r"(d[2]), "=r"(d[3]) : "r"(addr));
}
static __device__ __forceinline__ void mma16816(float* c, const uint32_t* a,
                                                uint32_t b0, uint32_t b1) {
    asm volatile("mma.sync.aligned.m16n8k16.row.col.f32.f16.f16.f32 "
                 "{%0,%1,%2,%3}, {%4,%5,%6,%7}, {%8,%9}, {%0,%1,%2,%3};"
                 : "+f"(c[0]), "+f"(c[1]), "+f"(c[2]), "+f"(c[3])
                 : "r"(a[0]), "r"(a[1]), "r"(a[2]), "r"(a[3]), "r"(b0), "r"(b1));
}

// ---------------- fused prep: transpose + W pack(+swizzle) + inv ----------------
// grid (17, BATCH+1). by < BATCH: transpose one (64c x 64h) tile of batch by.
// by == BATCH: 17 blocks handle W pack into pre-swizzled slot images + inv.
__global__ void prep_all(const float* __restrict__ x,
                         const float* __restrict__ wc, const float* __restrict__ wn,
                         const int* __restrict__ nb) {
    __shared__ float sm[64][65];
    const int b  = blockIdx.y;

    if (b == BATCH) {
        int t = blockIdx.x * 256 + threadIdx.x;           // 0..4351
        for (int u = t; u < COUT * KD; u += 17 * 256) {
            int o = u / KD, kk = u - o * KD;
            int s = kk >> 6, cc = kk & 63;
            float v = (s == 0) ? wc[o * CIN + cc] : wn[(o * CIN + cc) * KNB + (s - 1)];
            int unit = cc >> 3, e = cc & 7;
            size_t off = (size_t)s * A_CHUNK + o * 128 + ((unit ^ (o & 7)) * 16) + e * 2;
            *(__half*)(g_Wslot + off) = __float2half(v);
        }
        if (t < HX) {
            int cnt = 1;
#pragma unroll
            for (int k = 0; k < KNB; k++) cnt += (nb[t * KNB + k] >= 0) ? 1 : 0;
            g_invd[t] = 1.0f / (float)cnt;
        }
        return;
    }

    const int h0 = blockIdx.x * 64;
    const int lane = threadIdx.x & 31;
    const int w    = threadIdx.x >> 5;     // 0..7

    float v[16];
#pragma unroll
    for (int i = 0; i < 8; i++) {
        int c = w * 8 + i;
        const float* src = x + ((size_t)b * CIN + c) * HX + h0;
        v[2 * i]     = (h0 + lane < HX)      ? src[lane]      : 0.0f;
        v[2 * i + 1] = (h0 + 32 + lane < HX) ? src[32 + lane] : 0.0f;
    }
#pragma unroll
    for (int i = 0; i < 8; i++) {
        int c = w * 8 + i;
        sm[c][lane]      = v[2 * i];
        sm[c][32 + lane] = v[2 * i + 1];
    }
    __syncthreads();
#pragma unroll
    for (int i = 0; i < 8; i++) {
        int hh = w * 8 + i;
        int h = h0 + hh;
        if (h < HX) {
            __half2* dst = (__half2*)(g_xTh + ((size_t)b * HX + h) * CIN);
            dst[lane] = __floats2half2_rn(sm[2 * lane][hh], sm[2 * lane + 1][hh]);
        }
    }
}

// ---------------- produce one chunk via TMA bulk copies ----------------
static __device__ __forceinline__ void produce_chunk(uint32_t slot, uint32_t mbar,
                                                     const int* __restrict__ nb,
                                                     int b, int hbase, int s, int tid) {
    if (tid == 0) {
        MBARRIER_EXPECT_TX(mbar, TXBYTES);
        bulk_g2s(slot, g_Wslot + (size_t)s * A_CHUNK, A_CHUNK, mbar);
    }
    if (tid < 64) {
        int n = tid;
        int h = hbase + n;
        const void* src = (const void*)g_zero;
        if (h < HX) {
            int idx = (s == 0) ? h : __ldg(nb + h * KNB + (s - 1));
            if (idx >= 0) src = (const void*)(g_xTh + ((size_t)b * HX + idx) * CIN);
        }
        bulk_g2s(slot + A_CHUNK + (uint32_t)n * B_ROWP, src, 128, mbar);
    }
}

// ---------------- main persistent kernel: 256 thr, 2 CTAs/SM, tile 128x64 ----------------
// warp grid 4M x 2N, warp tile 32x32 (validated body); all fills via TMA bulk
__global__ void __launch_bounds__(256, 2)
hexconv_main(const int* __restrict__ nb, const float* __restrict__ bias,
             float* __restrict__ out) {
    extern __shared__ __align__(1024) char smem[];
    const uint32_t smBase = s2u(smem);
    const uint32_t smS = smBase + 1024;            // slots
    // mbarriers in header
    const int tid  = threadIdx.x;
    const int wid  = tid >> 5;
    const int lane = tid & 31;
    const int cta  = blockIdx.x;
    const int nC   = gridDim.x;

    if (tid == 0) {
#pragma unroll
        for (int q = 0; q < NSTAGE; q++) MBARRIER_INIT(smBase + q * 8, 1);
        FENCE_PROXY_ASYNC();
    }
    __syncthreads();

    const int ntiles_cta = (TOT_TILES - cta + nC - 1) / nC;
    const int nchunks = ntiles_cta * NSLOT;

    // ---- ahead cursor + prologue chunks ----
    int w_a = cta;
    int b_a = w_a / TPB;
    int hb_a = (w_a - b_a * TPB) * NTILE;
    int s_a = 0, q_a = 0;
#pragma unroll 1
    for (int j = 0; j < LOOKAHEAD && j < nchunks; j++) {
        produce_chunk(smS + (uint32_t)q_a * SLOT_B, smBase + q_a * 8, nb, b_a, hb_a, s_a, tid);
        if (++s_a == NSLOT) { s_a = 0; w_a += nC; b_a = w_a / TPB; hb_a = (w_a - b_a * TPB) * NTILE; }
        if (++q_a == NSTAGE) q_a = 0;
    }

    // ---- per-warp MMA constants ----
    const uint32_t m0 = (uint32_t)(wid & 3) * 32;
    const uint32_t n0 = (uint32_t)(wid >> 2) * 32;
    const uint32_t arow  = (lane & 7) + ((lane >> 3) & 1) * 8;
    const uint32_t aksel = (uint32_t)(lane >> 4);
    const uint32_t ar7   = arow & 7;
    const uint32_t aoff0 = (m0 + arow) * 128;                 // within A image
    const uint32_t nrow  = (lane & 7) + ((lane >> 4) & 1) * 8;
    const uint32_t bksel = (uint32_t)((lane >> 3) & 1);
    const uint32_t boff0 = A_CHUNK + (n0 + nrow) * B_ROWP;    // within slot (stride-144)

    // epilogue constants
    const int qq   = lane >> 2;
    const int col0 = 2 * (lane & 3);
    const float bia0 = bias[m0 + qq];
    const float bia1 = bias[m0 + qq + 8];
    const float bia2 = bias[m0 + qq + 16];
    const float bia3 = bias[m0 + qq + 24];

    // ---- consume cursor ----
    int w_c = cta;
    int b_c = w_c / TPB;
    int hb_c = (w_c - b_c * TPB) * NTILE;
    int s_c = 0, q_c = 0;

    float acc[2][4][4];
#pragma unroll
    for (int mf = 0; mf < 2; mf++)
#pragma unroll
        for (int nf = 0; nf < 4; nf++)
#pragma unroll
            for (int e = 0; e < 4; e++) acc[mf][nf][e] = 0.0f;

    for (int c = 0; c < nchunks; c++) {
        MBARRIER_WAIT_PARITY(smBase + q_c * 8, (uint32_t)((c / NSTAGE) & 1));
        __syncthreads();   // all warps past chunk c-1 reads -> slot q_a reusable

        if (c + LOOKAHEAD < nchunks) {
            produce_chunk(smS + (uint32_t)q_a * SLOT_B, smBase + q_a * 8, nb, b_a, hb_a, s_a, tid);
            if (++s_a == NSLOT) { s_a = 0; w_a += nC; b_a = w_a / TPB; hb_a = (w_a - b_a * TPB) * NTILE; }
            if (++q_a == NSTAGE) q_a = 0;
        }

        // ---- MMA: 4 k-steps on slot q_c ----
        const uint32_t slot = smS + (uint32_t)q_c * SLOT_B;
        const uint32_t a0base = slot + aoff0;
        const uint32_t b0base = slot + boff0;
#pragma unroll
        for (int ksl = 0; ksl < 4; ksl++) {
            uint32_t ua = (((2u * ksl + aksel) ^ ar7) * 16);
            uint32_t ub = ((2u * ksl + bksel) * 16);
            uint32_t aA[4], aB[4], bb0[4], bb1[4];
            ldsm4(aA, a0base + ua);
            ldsm4(aB, a0base + 16 * 128 + ua);
            ldsm4(bb0, b0base + ub);
            ldsm4(bb1, b0base + 16 * B_ROWP + ub);
            mma16816(acc[0][0], aA, bb0[0], bb0[1]);
            mma16816(acc[0][1], aA, bb0[2], bb0[3]);
            mma16816(acc[0][2], aA, bb1[0], bb1[1]);
            mma16816(acc[0][3], aA, bb1[2], bb1[3]);
            mma16816(acc[1][0], aB, bb0[0], bb0[1]);
            mma16816(acc[1][1], aB, bb0[2], bb0[3]);
            mma16816(acc[1][2], aB, bb1[0], bb1[1]);
            mma16816(acc[1][3], aB, bb1[2], bb1[3]);
        }
        if (++q_c == NSTAGE) q_c = 0;

        if (++s_c == NSLOT) {
            // ---- epilogue for tile (b_c, hb_c): scalar stores (HX odd) ----
            float* outB = out + (size_t)b_c * COUT * HX;
#pragma unroll
            for (int mf = 0; mf < 2; mf++) {
                const float blo = mf ? bia2 : bia0;
                const float bhi = mf ? bia3 : bia1;
                float* r0 = outB + (size_t)(m0 + 16 * mf + qq) * HX;
                float* r1 = r0 + 8 * (size_t)HX;
#pragma unroll
                for (int nf = 0; nf < 4; nf++) {
                    int hh = hb_c + (int)n0 + 8 * nf + col0;
                    if (hh < HX) {
                        float i0 = g_invd[hh];
                        r0[hh] = acc[mf][nf][0] * i0 + blo;
                        r1[hh] = acc[mf][nf][2] * i0 + bhi;
                    }
                    if (hh + 1 < HX) {
                        float i1 = g_invd[hh + 1];
                        r0[hh + 1] = acc[mf][nf][1] * i1 + blo;
                        r1[hh + 1] = acc[mf][nf][3] * i1 + bhi;
                    }
                }
            }
#pragma unroll
            for (int mf = 0; mf < 2; mf++)
#pragma unroll
                for (int nf = 0; nf < 4; nf++)
#pragma unroll
                    for (int e = 0; e < 4; e++) acc[mf][nf][e] = 0.0f;
            s_c = 0;
            w_c += nC;
            b_c = w_c / TPB;
            hb_c = (w_c - b_c * TPB) * NTILE;
        }
    }
}

// ---------------- launch ----------------
extern "C" void kernel_launch(void* const* d_in, const int* in_sizes, int n_in,
                              void* d_out, int out_size) {
    const float* x    = (const float*)d_in[0];
    const int*   nb   = (const int*)d_in[1];
    const float* wc   = (const float*)d_in[2];
    const float* wn   = (const float*)d_in[3];
    const float* bias = (const float*)d_in[4];
    float* out = (float*)d_out;

    int nsm = 148;
    cudaDeviceGetAttribute(&nsm, cudaDevAttrMultiProcessorCount, 0);

    cudaFuncSetAttribute(hexconv_main, cudaFuncAttributeMaxDynamicSharedMemorySize, SMEM_TOTAL);

    prep_all<<<dim3(17, BATCH + 1), 256>>>(x, wc, wn, nb);
    hexconv_main<<<2 * nsm, 256, SMEM_TOTAL>>>(nb, bias, out);
}

// round 16
// speedup vs baseline: 1.4248x; 1.4248x over previous
#include <cuda_runtime.h>
#include <cuda_fp16.h>
#include <cstdint>

// ---------------- problem constants ----------------
#define BATCH   256
#define CIN     64
#define COUT    128
#define HX      1039
#define KNB     6
#define NSLOT   7
#define KD      448          // k extent (7 slots * 64)
#define BH      (BATCH * HX)
#define NTILE   64           // h per CTA tile
#define TPB     17           // tiles per batch: ceil(1039/64)
#define TOT_TILES (BATCH * TPB)   // 4352

// slot = [A-slice image 16KB (TMA bulk)][B-gather 64 x 128B (cp.async, XOR swizzle)]
#define A_CHUNK   16384
#define B_CHUNK   8192
#define SLOT_B    (A_CHUNK + B_CHUNK)     // 24576
#define NSTAGE    4
#define LOOKAHEAD 3
#define SMEM_TOTAL (1024 + NSTAGE * SLOT_B)   // 99328 -> 2 CTAs/SM

// ---------------- scratch ----------------
__device__ __align__(16)  __half g_xTh[(size_t)BATCH * HX * CIN];  // [b][h][c], 128B rows
__device__ __align__(128) char   g_Wslot[NSLOT * A_CHUNK];         // pre-swizzled A images
__device__ float  g_invd[HX];

// ---------------- helpers ----------------
static __device__ __forceinline__ uint32_t s2u(const void* p) {
    uint32_t a;
    asm("{ .reg .u64 t; cvta.to.shared.u64 t, %1; cvt.u32.u64 %0, t; }" : "=r"(a) : "l"(p));
    return a;
}
static __device__ __forceinline__ void bulk_g2s(uint32_t dst, const void* src,
                                                uint32_t size, uint32_t mbar) {
    asm volatile("cp.async.bulk.shared::cluster.global.mbarrier::complete_tx::bytes "
                 "[%0], [%1], %2, [%3];"
                 :: "r"(dst), "l"(src), "r"(size), "r"(mbar) : "memory");
}
static __device__ __forceinline__ void cp16cg(uint32_t dst, const void* src, uint32_t sz) {
    asm volatile("cp.async.cg.shared.global [%0], [%1], 16, %2;"
                 :: "r"(dst), "l"(src), "r"(sz) : "memory");
}
static __device__ __forceinline__ void cp_commit() {
    asm volatile("cp.async.commit_group;" ::: "memory");
}
static __device__ __forceinline__ void cp_wait2() {
    asm volatile("cp.async.wait_group 2;" ::: "memory");
}
#define MBARRIER_INIT(mb, c) \
    asm volatile("mbarrier.init.shared.b64 [%0], %1;" :: "r"((uint32_t)(mb)), "r"((uint32_t)(c)) : "memory")
#define MBARRIER_EXPECT_TX(mb, tx) \
    asm volatile("mbarrier.arrive.expect_tx.shared.b64 _, [%0], %1;" \
                 :: "r"((uint32_t)(mb)), "r"((uint32_t)(tx)) : "memory")
#define FENCE_PROXY_ASYNC() asm volatile("fence.proxy.async.shared::cta;" ::: "memory")
#define MBARRIER_WAIT_PARITY(mb, ph) do { \
    uint32_t _mb = (uint32_t)(mb), _ph = (uint32_t)(ph), _done; \
    asm volatile("{\n\t.reg .pred p;\n\tmbarrier.try_wait.parity.acquire.cta.shared::cta.b64 p, [%1], %2;\n\t" \
                 "selp.b32 %0, 1, 0, p;\n\t}" : "=r"(_done) : "r"(_mb), "r"(_ph) : "memory"); \
    if (!_done) { \
        asm volatile("{\n\t.reg .pred P1;\n\tWL_%=:\n\t" \
                     "mbarrier.try_wait.parity.acquire.cta.shared::cta.b64 P1, [%0], %1, 0x989680;\n\t" \
                     "@P1 bra.uni WD_%=;\n\tbra.uni WL_%=;\n\tWD_%=:\n\t}" \
                     :: "r"(_mb), "r"(_ph) : "memory"); \
    } \
} while (0)
static __device__ __forceinline__ void ldsm4(uint32_t* d, uint32_t addr) {
    asm volatile("ldmatrix.sync.aligned.m8n8.x4.shared.b16 {%0,%1,%2,%3}, [%4];"
                 : "=r"(d[0]), "=r"(d[1]), "=r"(d[2]), "=r"(d[3]) : "r"(addr));
}
static __device__ __forceinline__ void mma16816(float* c, const uint32_t* a,
                                                uint32_t b0, uint32_t b1) {
    asm volatile("mma.sync.aligned.m16n8k16.row.col.f32.f16.f16.f32 "
                 "{%0,%1,%2,%3}, {%4,%5,%6,%7}, {%8,%9}, {%0,%1,%2,%3};"
                 : "+f"(c[0]), "+f"(c[1]), "+f"(c[2]), "+f"(c[3])
                 : "r"(a[0]), "r"(a[1]), "r"(a[2]), "r"(a[3]), "r"(b0), "r"(b1));
}

// ---------------- fused prep: transpose + W pack(pre-swizzled) + inv ----------------
__global__ void prep_all(const float* __restrict__ x,
                         const float* __restrict__ wc, const float* __restrict__ wn,
                         const int* __restrict__ nb) {
    __shared__ float sm[64][65];
    const int b  = blockIdx.y;

    if (b == BATCH) {
        int t = blockIdx.x * 256 + threadIdx.x;           // 0..4351
        for (int u = t; u < COUT * KD; u += 17 * 256) {
            int o = u / KD, kk = u - o * KD;
            int s = kk >> 6, cc = kk & 63;
            float v = (s == 0) ? wc[o * CIN + cc] : wn[(o * CIN + cc) * KNB + (s - 1)];
            int unit = cc >> 3, e = cc & 7;
            size_t off = (size_t)s * A_CHUNK + o * 128 + ((unit ^ (o & 7)) * 16) + e * 2;
            *(__half*)(g_Wslot + off) = __float2half(v);
        }
        if (t < HX) {
            int cnt = 1;
#pragma unroll
            for (int k = 0; k < KNB; k++) cnt += (nb[t * KNB + k] >= 0) ? 1 : 0;
            g_invd[t] = 1.0f / (float)cnt;
        }
        return;
    }

    const int h0 = blockIdx.x * 64;
    const int lane = threadIdx.x & 31;
    const int w    = threadIdx.x >> 5;     // 0..7

    float v[16];
#pragma unroll
    for (int i = 0; i < 8; i++) {
        int c = w * 8 + i;
        const float* src = x + ((size_t)b * CIN + c) * HX + h0;
        v[2 * i]     = (h0 + lane < HX)      ? src[lane]      : 0.0f;
        v[2 * i + 1] = (h0 + 32 + lane < HX) ? src[32 + lane] : 0.0f;
    }
#pragma unroll
    for (int i = 0; i < 8; i++) {
        int c = w * 8 + i;
        sm[c][lane]      = v[2 * i];
        sm[c][32 + lane] = v[2 * i + 1];
    }
    __syncthreads();
#pragma unroll
    for (int i = 0; i < 8; i++) {
        int hh = w * 8 + i;
        int h = h0 + hh;
        if (h < HX) {
            __half2* dst = (__half2*)(g_xTh + ((size_t)b * HX + h) * CIN);
            dst[lane] = __floats2half2_rn(sm[2 * lane][hh], sm[2 * lane + 1][hh]);
        }
    }
}

// ---------------- produce one chunk: A via one TMA bulk; B via cp.async gather ----------------
static __device__ __forceinline__ void produce_chunk(uint32_t slot, uint32_t mbar,
                                                     const int* __restrict__ nb,
                                                     int b, int hbase, int s, int tid) {
    if (tid == 0) {
        MBARRIER_EXPECT_TX(mbar, A_CHUNK);
        bulk_g2s(slot, g_Wslot + (size_t)s * A_CHUNK, A_CHUNK, mbar);
    }
    // B-gather: 64 rows x 128B (XOR swizzle), zero-fill masked/out-of-range
#pragma unroll
    for (int r = 0; r < 2; r++) {
        int u = tid + r * 256;            // 0..511
        int n = u >> 3;                   // row 0..63
        int jj = u & 7;
        int h = hbase + n;
        int idx = 0;
        uint32_t sz = 0;
        if (h < HX) {
            if (s == 0) { idx = h; sz = 16; }
            else {
                int t = __ldg(nb + h * KNB + (s - 1));
                if (t >= 0) { idx = t; sz = 16; }
            }
        }
        const char* src = (const char*)(g_xTh + ((size_t)b * HX + idx) * CIN) + jj * 16;
        uint32_t dst = slot + A_CHUNK + (uint32_t)(n * 128) + (uint32_t)((jj ^ (n & 7)) * 16);
        cp16cg(dst, src, sz);
    }
}

// ---------------- main persistent kernel: 256 thr, 2 CTAs/SM, tile 128x64 ----------------
// warp grid 4M x 2N, warp tile 32x32 (validated body)
__global__ void __launch_bounds__(256, 2)
hexconv_main(const int* __restrict__ nb, const float* __restrict__ bias,
             float* __restrict__ out) {
    extern __shared__ __align__(1024) char smem[];
    const uint32_t smBase = s2u(smem);
    const uint32_t smS = smBase + 1024;

    const int tid  = threadIdx.x;
    const int wid  = tid >> 5;
    const int lane = tid & 31;
    const int cta  = blockIdx.x;
    const int nC   = gridDim.x;

    if (tid == 0) {
#pragma unroll
        for (int q = 0; q < NSTAGE; q++) MBARRIER_INIT(smBase + q * 8, 1);
        FENCE_PROXY_ASYNC();
    }
    __syncthreads();

    const int ntiles_cta = (TOT_TILES - cta + nC - 1) / nC;
    const int nchunks = ntiles_cta * NSLOT;

    // ---- ahead cursor + prologue chunks ----
    int w_a = cta;
    int b_a = w_a / TPB;
    int hb_a = (w_a - b_a * TPB) * NTILE;
    int s_a = 0, q_a = 0;
#pragma unroll 1
    for (int j = 0; j < LOOKAHEAD; j++) {
        produce_chunk(smS + (uint32_t)q_a * SLOT_B, smBase + q_a * 8, nb, b_a, hb_a, s_a, tid);
        cp_commit();
        if (++s_a == NSLOT) { s_a = 0; w_a += nC; b_a = w_a / TPB; hb_a = (w_a - b_a * TPB) * NTILE; }
        if (++q_a == NSTAGE) q_a = 0;
    }

    // ---- per-warp MMA constants ----
    const uint32_t m0 = (uint32_t)(wid & 3) * 32;
    const uint32_t n0 = (uint32_t)(wid >> 2) * 32;
    const uint32_t arow  = (lane & 7) + ((lane >> 3) & 1) * 8;
    const uint32_t aksel = (uint32_t)(lane >> 4);
    const uint32_t ar7   = arow & 7;
    const uint32_t aoff0 = (m0 + arow) * 128;
    const uint32_t nrow  = (lane & 7) + ((lane >> 4) & 1) * 8;
    const uint32_t bksel = (uint32_t)((lane >> 3) & 1);
    const uint32_t br7   = nrow & 7;
    const uint32_t boff0 = A_CHUNK + (n0 + nrow) * 128;

    // epilogue constants
    const int qq   = lane >> 2;
    const int col0 = 2 * (lane & 3);
    const float bia0 = bias[m0 + qq];
    const float bia1 = bias[m0 + qq + 8];
    const float bia2 = bias[m0 + qq + 16];
    const float bia3 = bias[m0 + qq + 24];

    // ---- consume cursor ----
    int w_c = cta;
    int b_c = w_c / TPB;
    int hb_c = (w_c - b_c * TPB) * NTILE;
    int s_c = 0, q_c = 0;

    float acc[2][4][4];
#pragma unroll
    for (int mf = 0; mf < 2; mf++)
#pragma unroll
        for (int nf = 0; nf < 4; nf++)
#pragma unroll
            for (int e = 0; e < 4; e++) acc[mf][nf][e] = 0.0f;

    for (int c = 0; c < nchunks; c++) {
        MBARRIER_WAIT_PARITY(smBase + q_c * 8, (uint32_t)((c / NSTAGE) & 1));   // A image ready
        cp_wait2();                                                             // B gather ready
        __syncthreads();   // all warps past chunk c-1 reads -> slot q_a reusable

        if (c + LOOKAHEAD < nchunks) {
            produce_chunk(smS + (uint32_t)q_a * SLOT_B, smBase + q_a * 8, nb, b_a, hb_a, s_a, tid);
            if (++s_a == NSLOT) { s_a = 0; w_a += nC; b_a = w_a / TPB; hb_a = (w_a - b_a * TPB) * NTILE; }
            if (++q_a == NSTAGE) q_a = 0;
        }
        cp_commit();   // uniform group count

        // ---- MMA: 4 k-steps on slot q_c ----
        const uint32_t slot = smS + (uint32_t)q_c * SLOT_B;
        const uint32_t a0base = slot + aoff0;
        const uint32_t b0base = slot + boff0;
#pragma unroll
        for (int ksl = 0; ksl < 4; ksl++) {
            uint32_t ua = (((2u * ksl + aksel) ^ ar7) * 16);
            uint32_t ub = (((2u * ksl + bksel) ^ br7) * 16);
            uint32_t aA[4], aB[4], bb0[4], bb1[4];
            ldsm4(aA, a0base + ua);
            ldsm4(aB, a0base + 16 * 128 + ua);
            ldsm4(bb0, b0base + ub);
            ldsm4(bb1, b0base + 16 * 128 + ub);
            mma16816(acc[0][0], aA, bb0[0], bb0[1]);
            mma16816(acc[0][1], aA, bb0[2], bb0[3]);
            mma16816(acc[0][2], aA, bb1[0], bb1[1]);
            mma16816(acc[0][3], aA, bb1[2], bb1[3]);
            mma16816(acc[1][0], aB, bb0[0], bb0[1]);
            mma16816(acc[1][1], aB, bb0[2], bb0[3]);
            mma16816(acc[1][2], aB, bb1[0], bb1[1]);
            mma16816(acc[1][3], aB, bb1[2], bb1[3]);
        }
        if (++q_c == NSTAGE) q_c = 0;

        if (++s_c == NSLOT) {
            // ---- epilogue for tile (b_c, hb_c): scalar stores (HX odd) ----
            float* outB = out + (size_t)b_c * COUT * HX;
#pragma unroll
            for (int mf = 0; mf < 2; mf++) {
                const float blo = mf ? bia2 : bia0;
                const float bhi = mf ? bia3 : bia1;
                float* r0 = outB + (size_t)(m0 + 16 * mf + qq) * HX;
                float* r1 = r0 + 8 * (size_t)HX;
#pragma unroll
                for (int nf = 0; nf < 4; nf++) {
                    int hh = hb_c + (int)n0 + 8 * nf + col0;
                    if (hh < HX) {
                        float i0 = g_invd[hh];
                        r0[hh] = acc[mf][nf][0] * i0 + blo;
                        r1[hh] = acc[mf][nf][2] * i0 + bhi;
                    }
                    if (hh + 1 < HX) {
                        float i1 = g_invd[hh + 1];
                        r0[hh + 1] = acc[mf][nf][1] * i1 + blo;
                        r1[hh + 1] = acc[mf][nf][3] * i1 + bhi;
                    }
                }
            }
#pragma unroll
            for (int mf = 0; mf < 2; mf++)
#pragma unroll
                for (int nf = 0; nf < 4; nf++)
#pragma unroll
                    for (int e = 0; e < 4; e++) acc[mf][nf][e] = 0.0f;
            s_c = 0;
            w_c += nC;
            b_c = w_c / TPB;
            hb_c = (w_c - b_c * TPB) * NTILE;
        }
    }
}

// ---------------- launch ----------------
extern "C" void kernel_launch(void* const* d_in, const int* in_sizes, int n_in,
                              void* d_out, int out_size) {
    const float* x    = (const float*)d_in[0];
    const int*   nb   = (const int*)d_in[1];
    const float* wc   = (const float*)d_in[2];
    const float* wn   = (const float*)d_in[3];
    const float* bias = (const float*)d_in[4];
    float* out = (float*)d_out;

    int nsm = 148;
    cudaDeviceGetAttribute(&nsm, cudaDevAttrMultiProcessorCount, 0);

    cudaFuncSetAttribute(hexconv_main, cudaFuncAttributeMaxDynamicSharedMemorySize, SMEM_TOTAL);

    prep_all<<<dim3(17, BATCH + 1), 256>>>(x, wc, wn, nb);
    hexconv_main<<<2 * nsm, 256, SMEM_TOTAL>>>(nb, bias, out);
}